// round 9
// baseline (speedup 1.0000x reference)
#include <cuda_runtime.h>
#include <cstdint>

// ============================================================================
// GeneralRNN: h_t = hmlp([h_{t-1}, x_t]); y_t = ymlp(h_t)
//
// B=256, S=1024, D_IN=64, H=256, W_H=512, W_Y=256, D_OUT=64 (all fp32).
//
// Key structural fact: the recurrence is independent per batch row, so one
// persistent kernel with 64 CTAs x 4 rows each runs all 1024 steps with no
// inter-CTA sync. Weights (1.57 MB) stream from L2 each step. Inner products
// use Blackwell packed fp32 FMA (fma.rn.f32x2): activations are stored in
// smem as duplicated (v,v) u64 pairs so a single LDS.64 broadcast feeds the
// packed multiplicand directly; weights are loaded as u64 column pairs
// (fully coalesced 256B/warp).
// ============================================================================

#define ULL unsigned long long

static constexpr int B    = 256;
static constexpr int S    = 1024;
static constexpr int DIN  = 64;
static constexpr int H    = 256;
static constexpr int WH   = 512;
static constexpr int WY   = 256;
static constexpr int DOUT = 64;
static constexpr int KHX  = H + DIN;   // 320

static constexpr int NCTA = 64;
static constexpr int M    = 4;         // batch rows per CTA
static constexpr int T    = 256;       // threads per CTA

// ---- packed f32x2 helpers (sm_100+) ----------------------------------------
__device__ __forceinline__ void ffma2(ULL& c, ULL a, ULL b) {
    // c = a * b + c, elementwise on packed {f32,f32}
    asm("fma.rn.f32x2 %0, %1, %2, %0;" : "+l"(c) : "l"(a), "l"(b));
}
__device__ __forceinline__ ULL fadd2(ULL a, ULL b) {
    ULL r; asm("add.rn.f32x2 %0, %1, %2;" : "=l"(r) : "l"(a), "l"(b)); return r;
}
__device__ __forceinline__ ULL pack2(float lo, float hi) {
    ULL r;
    asm("mov.b64 %0, {%1, %2};"
        : "=l"(r) : "r"(__float_as_uint(lo)), "r"(__float_as_uint(hi)));
    return r;
}
__device__ __forceinline__ void unpack2(ULL v, float& lo, float& hi) {
    unsigned int a, b;
    asm("mov.b64 {%0, %1}, %2;" : "=r"(a), "=r"(b) : "l"(v));
    lo = __uint_as_float(a); hi = __uint_as_float(b);
}
__device__ __forceinline__ float silu_f(float z) {
    return z / (1.0f + __expf(-z));
}

__global__ __launch_bounds__(T, 1)
void rnn_persistent_kernel(
    const float* __restrict__ x,    // [B, S, DIN]
    const float* __restrict__ W1h,  // [KHX, WH]
    const float* __restrict__ b1h,  // [WH]
    const float* __restrict__ W2h,  // [WH, H]
    const float* __restrict__ b2h,  // [H]
    const float* __restrict__ W1y,  // [H, WY]
    const float* __restrict__ b1y,  // [WY]
    const float* __restrict__ W2y,  // [WY, DOUT]
    const float* __restrict__ b2y,  // [DOUT]
    float* __restrict__ outs,       // [B, S, DOUT]
    float* __restrict__ hid)        // [S+1, B, H]
{
    // All activation buffers hold duplicated packed pairs (v,v) so they can be
    // consumed directly as the broadcast operand of fma.rn.f32x2.
    __shared__ ULL hx2[M][KHX];        // [h | x_t]  (cols 0..255 = h, 256..319 = x)
    __shared__ ULL a2 [M][WH];         // silu(layer-1 of hmlp)
    __shared__ ULL yh2[M][WY];         // silu(layer-1 of ymlp)
    __shared__ ULL red [M][H / 2];     // split-K reduction buffer (phases 2,3)
    __shared__ ULL red4[8][M][DOUT/2]; // split-K reduction buffer (phase 4)

    const int tid = threadIdx.x;
    const int b0  = blockIdx.x * M;

    // h0 = 0; hiddens[0] = 0
    for (int i = tid; i < M * H; i += T) {
        const int m = i / H, j = i % H;
        hx2[m][j] = 0ULL;
        hid[(size_t)(b0 + m) * H + j] = 0.0f;
    }
    __syncthreads();

    for (int t = 0; t < S; ++t) {
        // ---- load x_t into hx columns [H, H+DIN) --------------------------
        {
            const int m = tid >> 6, d = tid & 63;     // 4 x 64 = 256 threads
            const float xv = x[((size_t)(b0 + m) * S + t) * DIN + d];
            hx2[m][H + d] = pack2(xv, xv);
        }
        __syncthreads();

        // ---- phase 1: a = silu(hx @ W1h + b1h)  (K=320, N=512) ------------
        // thread j owns output column pair (2j, 2j+1) for all M rows
        {
            const int j2 = 2 * tid;
            ULL acc[M];
            const ULL bias = *(const ULL*)(b1h + j2);
            #pragma unroll
            for (int m = 0; m < M; ++m) acc[m] = bias;

            const float* wp = W1h + j2;
            #pragma unroll 4
            for (int k = 0; k < KHX; ++k) {
                const ULL w = *(const ULL*)(wp + (size_t)k * WH);
                #pragma unroll
                for (int m = 0; m < M; ++m) ffma2(acc[m], hx2[m][k], w);
            }
            #pragma unroll
            for (int m = 0; m < M; ++m) {
                float z0, z1; unpack2(acc[m], z0, z1);
                const float s0 = silu_f(z0), s1 = silu_f(z1);
                a2[m][j2]     = pack2(s0, s0);
                a2[m][j2 + 1] = pack2(s1, s1);
            }
        }
        __syncthreads();

        // ---- phase 2: h' = a @ W2h + b2h  (K=512 split 2-way, N=256) ------
        {
            const int jj = tid & 127, half = tid >> 7;
            const int j2 = 2 * jj;
            ULL acc[M];
            if (half == 0) {
                const ULL bias = *(const ULL*)(b2h + j2);
                #pragma unroll
                for (int m = 0; m < M; ++m) acc[m] = bias;
            } else {
                #pragma unroll
                for (int m = 0; m < M; ++m) acc[m] = 0ULL;
            }
            const int k0 = half * 256;
            const float* wp = W2h + j2;
            #pragma unroll 4
            for (int k = k0; k < k0 + 256; ++k) {
                const ULL w = *(const ULL*)(wp + (size_t)k * H);
                #pragma unroll
                for (int m = 0; m < M; ++m) ffma2(acc[m], a2[m][k], w);
            }
            if (half == 1) {
                #pragma unroll
                for (int m = 0; m < M; ++m) red[m][jj] = acc[m];
            }
            __syncthreads();
            if (half == 0) {
                #pragma unroll
                for (int m = 0; m < M; ++m) {
                    const ULL v = fadd2(acc[m], red[m][jj]);
                    float h0f, h1f; unpack2(v, h0f, h1f);
                    // hiddens[t+1][b0+m][j2..j2+1]
                    *(float2*)(hid + ((size_t)(t + 1) * B + (b0 + m)) * H + j2)
                        = make_float2(h0f, h1f);
                    // h for next step's phase 1 AND this step's phase 3
                    hx2[m][j2]     = pack2(h0f, h0f);
                    hx2[m][j2 + 1] = pack2(h1f, h1f);
                }
            }
        }
        __syncthreads();

        // ---- phase 3: yh = silu(h' @ W1y + b1y)  (K=256 split 2-way) ------
        {
            const int jj = tid & 127, half = tid >> 7;
            const int j2 = 2 * jj;
            ULL acc[M];
            if (half == 0) {
                const ULL bias = *(const ULL*)(b1y + j2);
                #pragma unroll
                for (int m = 0; m < M; ++m) acc[m] = bias;
            } else {
                #pragma unroll
                for (int m = 0; m < M; ++m) acc[m] = 0ULL;
            }
            const int k0 = half * 128;
            const float* wp = W1y + j2;
            #pragma unroll 4
            for (int k = k0; k < k0 + 128; ++k) {
                const ULL w = *(const ULL*)(wp + (size_t)k * WY);
                #pragma unroll
                for (int m = 0; m < M; ++m) ffma2(acc[m], hx2[m][k], w);
            }
            if (half == 1) {
                #pragma unroll
                for (int m = 0; m < M; ++m) red[m][jj] = acc[m];
            }
            __syncthreads();
            if (half == 0) {
                #pragma unroll
                for (int m = 0; m < M; ++m) {
                    const ULL v = fadd2(acc[m], red[m][jj]);
                    float z0, z1; unpack2(v, z0, z1);
                    const float s0 = silu_f(z0), s1 = silu_f(z1);
                    yh2[m][j2]     = pack2(s0, s0);
                    yh2[m][j2 + 1] = pack2(s1, s1);
                }
            }
        }
        __syncthreads();

        // ---- phase 4: y = yh @ W2y + b2y  (K=256 split 8-way, N=64) -------
        {
            const int cp = tid & 31, oct = tid >> 5;
            const int j2 = 2 * cp;
            ULL acc[M];
            #pragma unroll
            for (int m = 0; m < M; ++m) acc[m] = 0ULL;
            const int k0 = oct * 32;
            const float* wp = W2y + j2;
            #pragma unroll 4
            for (int k = k0; k < k0 + 32; ++k) {
                const ULL w = *(const ULL*)(wp + (size_t)k * DOUT);
                #pragma unroll
                for (int m = 0; m < M; ++m) ffma2(acc[m], yh2[m][k], w);
            }
            #pragma unroll
            for (int m = 0; m < M; ++m) red4[oct][m][cp] = acc[m];
            __syncthreads();
            if (oct == 0) {
                #pragma unroll
                for (int m = 0; m < M; ++m) {
                    ULL v = acc[m];
                    #pragma unroll
                    for (int o = 1; o < 8; ++o) v = fadd2(v, red4[o][m][cp]);
                    v = fadd2(v, *(const ULL*)(b2y + j2));
                    float y0, y1; unpack2(v, y0, y1);
                    *(float2*)(outs + ((size_t)(b0 + m) * S + t) * DOUT + j2)
                        = make_float2(y0, y1);
                }
            }
        }
        __syncthreads();   // guard smem buffer reuse across iterations
    }
}

extern "C" void kernel_launch(void* const* d_in, const int* in_sizes, int n_in,
                              void* d_out, int out_size) {
    (void)in_sizes; (void)n_in; (void)out_size;
    const float* x   = (const float*)d_in[0];
    const float* W1h = (const float*)d_in[1];
    const float* b1h = (const float*)d_in[2];
    const float* W2h = (const float*)d_in[3];
    const float* b2h = (const float*)d_in[4];
    const float* W1y = (const float*)d_in[5];
    const float* b1y = (const float*)d_in[6];
    const float* W2y = (const float*)d_in[7];
    const float* b2y = (const float*)d_in[8];

    float* outs = (float*)d_out;                       // [B, S, DOUT]
    float* hid  = outs + (size_t)B * S * DOUT;         // [S+1, B, H]

    rnn_persistent_kernel<<<NCTA, T>>>(x, W1h, b1h, W2h, b2h,
                                       W1y, b1y, W2y, b2y, outs, hid);
}

// round 13
// speedup vs baseline: 1.7851x; 1.7851x over previous
#include <cuda_runtime.h>
#include <cstdint>

// ============================================================================
// GeneralRNN: h_t = hmlp([h_{t-1}, x_t]); y_t = ymlp(h_t)
// B=256, S=1024, D_IN=64, H=256, W_H=512, W_Y=256, D_OUT=64 (fp32).
//
// Persistent kernel, 64 CTAs x 4 batch rows, no inter-CTA sync (recurrence is
// per-row independent). R10 change vs R9: the weight-streaming inner products
// are software-pipelined with a 2x16 register double buffer (16 LDG.64 in
// flight per thread while the other 16 are consumed), and activation reads use
// 128-bit broadcast LDS covering two k's. This hides the ~250-cycle L2 latency
// that made R9 run at 7% fma / 9% L2.
// ============================================================================

#define ULL unsigned long long

static constexpr int B    = 256;
static constexpr int S    = 1024;
static constexpr int DIN  = 64;
static constexpr int H    = 256;
static constexpr int WH   = 512;
static constexpr int WY   = 256;
static constexpr int DOUT = 64;
static constexpr int KHX  = H + DIN;   // 320

static constexpr int NCTA = 64;
static constexpr int M    = 4;         // batch rows per CTA
static constexpr int T    = 256;       // threads per CTA

// ---- packed f32x2 helpers (sm_100+) ----------------------------------------
__device__ __forceinline__ void ffma2(ULL& c, ULL a, ULL b) {
    asm("fma.rn.f32x2 %0, %1, %2, %0;" : "+l"(c) : "l"(a), "l"(b));
}
__device__ __forceinline__ ULL fadd2(ULL a, ULL b) {
    ULL r; asm("add.rn.f32x2 %0, %1, %2;" : "=l"(r) : "l"(a), "l"(b)); return r;
}
__device__ __forceinline__ ULL pack2(float lo, float hi) {
    ULL r;
    asm("mov.b64 %0, {%1, %2};"
        : "=l"(r) : "r"(__float_as_uint(lo)), "r"(__float_as_uint(hi)));
    return r;
}
__device__ __forceinline__ void unpack2(ULL v, float& lo, float& hi) {
    unsigned int a, b;
    asm("mov.b64 {%0, %1}, %2;" : "=r"(a), "=r"(b) : "l"(v));
    lo = __uint_as_float(a); hi = __uint_as_float(b);
}
__device__ __forceinline__ float silu_f(float z) {
    return z / (1.0f + __expf(-z));
}
__device__ __forceinline__ ULL ldgw(const float* p) {   // read-only 64-bit weight load
    return __ldg(reinterpret_cast<const ULL*>(p));
}

// ----------------------------------------------------------------------------
// Pipelined dot product over KLEN weight rows for M batch rows.
//   acc[m] += sum_k act[m*ASTRIDE + k] (*packed dup*) * W2cols(wp + k*WSTRIDE)
// Register double buffer: while buffer A is consumed, buffer B's 16 loads are
// in flight. KLEN must be a multiple of 32. Activation base must be 16B
// aligned with even k offsets (LDS.128 broadcast reads two k's at once).
// ----------------------------------------------------------------------------
template<int KLEN, int WSTRIDE, int ASTRIDE>
__device__ __forceinline__ void dotp(ULL acc[M],
                                     const float* __restrict__ wp,
                                     const ULL* __restrict__ act)
{
    constexpr int U = 16;
    static_assert(KLEN % (2 * U) == 0, "KLEN must be multiple of 32");
    ULL wa[U], wb[U];

    #pragma unroll
    for (int u = 0; u < U; ++u) wa[u] = ldgw(wp + (size_t)u * WSTRIDE);

    #pragma unroll 1
    for (int k0 = 0; k0 < KLEN; k0 += 2 * U) {
        // prefetch buffer B (k0+U .. k0+2U-1) — always in range
        #pragma unroll
        for (int u = 0; u < U; ++u)
            wb[u] = ldgw(wp + (size_t)(k0 + U + u) * WSTRIDE);

        // consume buffer A
        #pragma unroll
        for (int u = 0; u < U; u += 2) {
            #pragma unroll
            for (int m = 0; m < M; ++m) {
                const ulonglong2 hv =
                    *reinterpret_cast<const ulonglong2*>(act + m * ASTRIDE + k0 + u);
                ffma2(acc[m], hv.x, wa[u]);
                ffma2(acc[m], hv.y, wa[u + 1]);
            }
        }

        // prefetch buffer A for next iteration (guarded at the tail)
        #pragma unroll
        for (int u = 0; u < U; ++u) {
            const int kk = k0 + 2 * U + u;
            if (kk < KLEN) wa[u] = ldgw(wp + (size_t)kk * WSTRIDE);
        }

        // consume buffer B
        #pragma unroll
        for (int u = 0; u < U; u += 2) {
            #pragma unroll
            for (int m = 0; m < M; ++m) {
                const ulonglong2 hv =
                    *reinterpret_cast<const ulonglong2*>(act + m * ASTRIDE + k0 + U + u);
                ffma2(acc[m], hv.x, wb[u]);
                ffma2(acc[m], hv.y, wb[u + 1]);
            }
        }
    }
}

__global__ __launch_bounds__(T, 1)
void rnn_persistent_kernel(
    const float* __restrict__ x,    // [B, S, DIN]
    const float* __restrict__ W1h,  // [KHX, WH]
    const float* __restrict__ b1h,  // [WH]
    const float* __restrict__ W2h,  // [WH, H]
    const float* __restrict__ b2h,  // [H]
    const float* __restrict__ W1y,  // [H, WY]
    const float* __restrict__ b1y,  // [WY]
    const float* __restrict__ W2y,  // [WY, DOUT]
    const float* __restrict__ b2y,  // [DOUT]
    float* __restrict__ outs,       // [B, S, DOUT]
    float* __restrict__ hid)        // [S+1, B, H]
{
    // Activation buffers hold duplicated packed pairs (v,v): one LDS broadcast
    // feeds fma.rn.f32x2 directly. 16B aligned for LDS.128 paired-k reads.
    __shared__ __align__(16) ULL hx2[M][KHX];        // [h | x_t]
    __shared__ __align__(16) ULL a2 [M][WH];         // silu(hmlp layer 1)
    __shared__ __align__(16) ULL yh2[M][WY];         // silu(ymlp layer 1)
    __shared__ __align__(16) ULL red [M][H / 2];     // split-K reduction (ph 2,3)
    __shared__ __align__(16) ULL red4[8][M][DOUT/2]; // split-K reduction (ph 4)

    const int tid = threadIdx.x;
    const int b0  = blockIdx.x * M;

    // h0 = 0; hiddens[0] = 0
    for (int i = tid; i < M * H; i += T) {
        const int m = i / H, j = i % H;
        hx2[m][j] = 0ULL;
        hid[(size_t)(b0 + m) * H + j] = 0.0f;
    }
    __syncthreads();

    for (int t = 0; t < S; ++t) {
        // ---- load x_t into hx columns [H, H+DIN) --------------------------
        {
            const int m = tid >> 6, d = tid & 63;     // 4 x 64 = 256 threads
            const float xv = x[((size_t)(b0 + m) * S + t) * DIN + d];
            hx2[m][H + d] = pack2(xv, xv);
        }
        __syncthreads();

        // ---- phase 1: a = silu(hx @ W1h + b1h)  (K=320, N=512) ------------
        {
            const int j2 = 2 * tid;
            ULL acc[M];
            const ULL bias = *(const ULL*)(b1h + j2);
            #pragma unroll
            for (int m = 0; m < M; ++m) acc[m] = bias;

            dotp<KHX, WH, KHX>(acc, W1h + j2, &hx2[0][0]);

            #pragma unroll
            for (int m = 0; m < M; ++m) {
                float z0, z1; unpack2(acc[m], z0, z1);
                const float s0 = silu_f(z0), s1 = silu_f(z1);
                a2[m][j2]     = pack2(s0, s0);
                a2[m][j2 + 1] = pack2(s1, s1);
            }
        }
        __syncthreads();

        // ---- phase 2: h' = a @ W2h + b2h  (K=512 split 2-way, N=256) ------
        {
            const int jj = tid & 127, half = tid >> 7;
            const int j2 = 2 * jj;
            ULL acc[M];
            if (half == 0) {
                const ULL bias = *(const ULL*)(b2h + j2);
                #pragma unroll
                for (int m = 0; m < M; ++m) acc[m] = bias;
            } else {
                #pragma unroll
                for (int m = 0; m < M; ++m) acc[m] = 0ULL;
            }
            dotp<256, H, WH>(acc, W2h + (size_t)(half * 256) * H + j2,
                             &a2[0][0] + half * 256);

            if (half == 1) {
                #pragma unroll
                for (int m = 0; m < M; ++m) red[m][jj] = acc[m];
            }
            __syncthreads();
            if (half == 0) {
                #pragma unroll
                for (int m = 0; m < M; ++m) {
                    const ULL v = fadd2(acc[m], red[m][jj]);
                    float h0f, h1f; unpack2(v, h0f, h1f);
                    *(float2*)(hid + ((size_t)(t + 1) * B + (b0 + m)) * H + j2)
                        = make_float2(h0f, h1f);
                    hx2[m][j2]     = pack2(h0f, h0f);
                    hx2[m][j2 + 1] = pack2(h1f, h1f);
                }
            }
        }
        __syncthreads();

        // ---- phase 3: yh = silu(h' @ W1y + b1y)  (K=256 split 2-way) ------
        {
            const int jj = tid & 127, half = tid >> 7;
            const int j2 = 2 * jj;
            ULL acc[M];
            if (half == 0) {
                const ULL bias = *(const ULL*)(b1y + j2);
                #pragma unroll
                for (int m = 0; m < M; ++m) acc[m] = bias;
            } else {
                #pragma unroll
                for (int m = 0; m < M; ++m) acc[m] = 0ULL;
            }
            dotp<128, WY, KHX>(acc, W1y + (size_t)(half * 128) * WY + j2,
                               &hx2[0][0] + half * 128);

            if (half == 1) {
                #pragma unroll
                for (int m = 0; m < M; ++m) red[m][jj] = acc[m];
            }
            __syncthreads();
            if (half == 0) {
                #pragma unroll
                for (int m = 0; m < M; ++m) {
                    const ULL v = fadd2(acc[m], red[m][jj]);
                    float z0, z1; unpack2(v, z0, z1);
                    const float s0 = silu_f(z0), s1 = silu_f(z1);
                    yh2[m][j2]     = pack2(s0, s0);
                    yh2[m][j2 + 1] = pack2(s1, s1);
                }
            }
        }
        __syncthreads();

        // ---- phase 4: y = yh @ W2y + b2y  (K=256 split 8-way, N=64) -------
        {
            const int cp = tid & 31, oct = tid >> 5;
            const int j2 = 2 * cp;
            ULL acc[M];
            #pragma unroll
            for (int m = 0; m < M; ++m) acc[m] = 0ULL;

            dotp<32, DOUT, WY>(acc, W2y + (size_t)(oct * 32) * DOUT + j2,
                               &yh2[0][0] + oct * 32);

            #pragma unroll
            for (int m = 0; m < M; ++m) red4[oct][m][cp] = acc[m];
            __syncthreads();
            if (oct == 0) {
                #pragma unroll
                for (int m = 0; m < M; ++m) {
                    ULL v = acc[m];
                    #pragma unroll
                    for (int o = 1; o < 8; ++o) v = fadd2(v, red4[o][m][cp]);
                    v = fadd2(v, *(const ULL*)(b2y + j2));
                    float y0, y1; unpack2(v, y0, y1);
                    *(float2*)(outs + ((size_t)(b0 + m) * S + t) * DOUT + j2)
                        = make_float2(y0, y1);
                }
            }
        }
        __syncthreads();   // guard smem buffer reuse across iterations
    }
}

extern "C" void kernel_launch(void* const* d_in, const int* in_sizes, int n_in,
                              void* d_out, int out_size) {
    (void)in_sizes; (void)n_in; (void)out_size;
    const float* x   = (const float*)d_in[0];
    const float* W1h = (const float*)d_in[1];
    const float* b1h = (const float*)d_in[2];
    const float* W2h = (const float*)d_in[3];
    const float* b2h = (const float*)d_in[4];
    const float* W1y = (const float*)d_in[5];
    const float* b1y = (const float*)d_in[6];
    const float* W2y = (const float*)d_in[7];
    const float* b2y = (const float*)d_in[8];

    float* outs = (float*)d_out;                       // [B, S, DOUT]
    float* hid  = outs + (size_t)B * S * DOUT;         // [S+1, B, H]

    rnn_persistent_kernel<<<NCTA, T>>>(x, W1h, b1h, W2h, b2h,
                                       W1y, b1y, W2y, b2y, outs, hid);
}